// round 4
// baseline (speedup 1.0000x reference)
#include <cuda_runtime.h>

#define N_NODES   40000
#define DEGREE    32
#define E_TOTAL   (N_NODES * DEGREE)
#define D         64
#define TILE_E    128                   // edges per block = 4 whole nodes
#define NODES_PB  4
#define NBLK      (E_TOTAL / TILE_E)    // 10000

// scratch (static __device__ allocation is allowed)
__device__ float g_gq[N_NODES * D];     // per-node query-side preactivation (incl. b1)
__device__ float g_w1a_t[D * D];        // att1_w[:, :64] transposed -> [k][f]
__device__ float g_w1b_t[D * D];        // att1_w[:, 64:] transposed -> [k][f]
__device__ float g_w2_t [D * D];        // att2_w transposed -> [k][f]

// ---------------------------------------------------------------------------
// Kernel 0: transpose weights into k-major layout (tiny, runs once per replay)
// ---------------------------------------------------------------------------
__global__ void k_transpose(const float* __restrict__ w1,
                            const float* __restrict__ w2) {
    int idx = blockIdx.x * blockDim.x + threadIdx.x;
    if (idx < D * D) {
        int f = idx / D, k = idx % D;          // coalesced reads along k
        g_w1a_t[k * D + f] = w1[f * 2 * D + k];
        g_w1b_t[k * D + f] = w1[f * 2 * D + D + k];
        g_w2_t [k * D + f] = w2[f * D + k];
    }
}

// ---------------------------------------------------------------------------
// Kernel 1: gq[n][f] = b1[f] + sum_k g2e[nodes[n]][k] * W1b[f][k]
// 16 nodes per 256-thread block
// ---------------------------------------------------------------------------
__global__ __launch_bounds__(256) void k_gq(const int* __restrict__ nodes,
                                            const float* __restrict__ g2e,
                                            const float* __restrict__ b1) {
    __shared__ float s_w[D * D];    // 16 KB, [k][f]
    __shared__ float s_g[16 * D];   // 4 KB
    int t = threadIdx.x;
    int nbase = blockIdx.x * 16;

    {   // vectorized staging
        const float4* w4 = (const float4*)g_w1b_t;
        float4* s4 = (float4*)s_w;
#pragma unroll
        for (int i = t; i < D * D / 4; i += 256) s4[i] = w4[i];
    }
    for (int i = t; i < 16 * 16; i += 256) {       // 16 nodes x 16 float4
        int nl = i >> 4, c = i & 15;
        ((float4*)s_g)[(nl << 4) + c] =
            ((const float4*)g2e)[(size_t)nodes[nbase + nl] * 16 + c];
    }
    __syncthreads();

    int f = t & 63, ng = t >> 6;    // thread handles nodes ng, ng+4, ng+8, ng+12
    float bias = b1[f];
    float acc[4] = {bias, bias, bias, bias};
    for (int k = 0; k < D; k++) {
        float w = s_w[k * D + f];
#pragma unroll
        for (int j = 0; j < 4; j++)
            acc[j] += w * s_g[(ng + 4 * j) * D + k];
    }
#pragma unroll
    for (int j = 0; j < 4; j++)
        g_gq[(size_t)(nbase + ng + 4 * j) * D + f] = acc[j];
}

// ---------------------------------------------------------------------------
// Register-tile GEMM step: 8 edges x 4 features per thread, k-unrolled by 4
// s_in: [128][64] activations, s_w: [64 k][64 f]
// ---------------------------------------------------------------------------
__device__ __forceinline__ void gemm_tile(const float* __restrict__ s_in,
                                          const float* __restrict__ s_w,
                                          float acc[8][4], int ebase, int tf) {
#pragma unroll 2
    for (int k = 0; k < D; k += 4) {
        float4 wa = *(const float4*)(s_w + (k + 0) * D + tf * 4);
        float4 wb = *(const float4*)(s_w + (k + 1) * D + tf * 4);
        float4 wc = *(const float4*)(s_w + (k + 2) * D + tf * 4);
        float4 wd = *(const float4*)(s_w + (k + 3) * D + tf * 4);
#pragma unroll
        for (int i = 0; i < 8; i++) {
            float4 ev = *(const float4*)(s_in + (ebase + i) * D + k);
            acc[i][0] += ev.x * wa.x; acc[i][1] += ev.x * wa.y;
            acc[i][2] += ev.x * wa.z; acc[i][3] += ev.x * wa.w;
            acc[i][0] += ev.y * wb.x; acc[i][1] += ev.y * wb.y;
            acc[i][2] += ev.y * wb.z; acc[i][3] += ev.y * wb.w;
            acc[i][0] += ev.z * wc.x; acc[i][1] += ev.z * wc.y;
            acc[i][2] += ev.z * wc.z; acc[i][3] += ev.z * wc.w;
            acc[i][0] += ev.w * wd.x; acc[i][1] += ev.w * wd.y;
            acc[i][2] += ev.w * wd.z; acc[i][3] += ev.w * wd.w;
        }
    }
}

// ---------------------------------------------------------------------------
// Kernel 2: fused edge MLP + segment softmax + weighted aggregation.
// Block = 128 edges = 4 whole nodes. 256 threads.
// ---------------------------------------------------------------------------
// dynamic smem layout (floats):
//   s_eu    [0,      8192)   128x64 gathered member embeddings
//   s_h1    [8192,  16384)   128x64 layer-1 activations
//   s_w1    [16384, 20480)   W1a_t
//   s_w2    [20480, 24576)   W2_t
//   s_gq    [24576, 24832)   4x64
//   s_b2    [24832, 24896)
//   s_w3    [24896, 24960)
//   s_logit [24960, 25088)
//   s_att   [25088, 25216)
#define SMEM_FLOATS 25216

__global__ __launch_bounds__(256, 2) void k_main(const int*   __restrict__ neigh,
                                                 const float* __restrict__ u2e,
                                                 const float* __restrict__ b2v,
                                                 const float* __restrict__ w3v,
                                                 const float* __restrict__ b3v,
                                                 float* __restrict__ out) {
    extern __shared__ float sm[];
    float* s_eu    = sm;
    float* s_h1    = sm + 8192;
    float* s_w1    = sm + 16384;
    float* s_w2    = sm + 20480;
    float* s_gq    = sm + 24576;
    float* s_b2    = sm + 24832;
    float* s_w3    = sm + 24896;
    float* s_logit = sm + 24960;
    float* s_att   = sm + 25088;

    int t  = threadIdx.x;
    int e0 = blockIdx.x * TILE_E;
    int n0 = blockIdx.x * NODES_PB;

    // stage weights (vectorized) / per-node query terms
    {
        const float4* w1v = (const float4*)g_w1a_t;
        const float4* w2v = (const float4*)g_w2_t;
        float4* d1 = (float4*)s_w1;
        float4* d2 = (float4*)s_w2;
#pragma unroll
        for (int i = t; i < D * D / 4; i += 256) {
            d1[i] = w1v[i];
            d2[i] = w2v[i];
        }
    }
    if (t < 64) { s_b2[t] = b2v[t]; s_w3[t] = w3v[t]; }
    s_gq[t] = g_gq[(size_t)n0 * D + t];          // 256 = 4*64
    float b3 = b3v[0];

    // gather member embeddings: 128 rows x 16 float4
    {
        const float4* u2e4 = (const float4*)u2e;
        float4* s_eu4 = (float4*)s_eu;
#pragma unroll
        for (int i = t; i < 2048; i += 256) {
            int r = i >> 4, c = i & 15;
            int uid = neigh[e0 + r];
            s_eu4[(r << 4) + c] = u2e4[(size_t)uid * 16 + c];
        }
    }
    __syncthreads();

    int tf    = t & 15;      // feature quad  (f = 4*tf .. 4*tf+3)
    int te    = t >> 4;      // edge group    (edges te*8 .. te*8+7)
    int ebase = te * 8;
    int nloc  = te >> 2;     // all 8 edges belong to this local node

    float acc[8][4];

    // ---- layer 1: h1 = relu(e_u @ W1a^T + gq[node]) ----
    {
        float4 q = ((const float4*)s_gq)[nloc * 16 + tf];
#pragma unroll
        for (int i = 0; i < 8; i++) {
            acc[i][0] = q.x; acc[i][1] = q.y; acc[i][2] = q.z; acc[i][3] = q.w;
        }
    }
    gemm_tile(s_eu, s_w1, acc, ebase, tf);
#pragma unroll
    for (int i = 0; i < 8; i++) {
        float4 v;
        v.x = fmaxf(acc[i][0], 0.f); v.y = fmaxf(acc[i][1], 0.f);
        v.z = fmaxf(acc[i][2], 0.f); v.w = fmaxf(acc[i][3], 0.f);
        *(float4*)(s_h1 + (ebase + i) * D + tf * 4) = v;
    }
    __syncthreads();

    // ---- layer 2: h2 = relu(h1 @ W2^T + b2), then logits = h2 . w3 + b3 ----
    {
        float4 b = ((const float4*)s_b2)[tf];
#pragma unroll
        for (int i = 0; i < 8; i++) {
            acc[i][0] = b.x; acc[i][1] = b.y; acc[i][2] = b.z; acc[i][3] = b.w;
        }
    }
    gemm_tile(s_h1, s_w2, acc, ebase, tf);

    float part[8];
    {
        float4 w3q = ((const float4*)s_w3)[tf];
#pragma unroll
        for (int i = 0; i < 8; i++) {
            part[i] = fmaxf(acc[i][0], 0.f) * w3q.x
                    + fmaxf(acc[i][1], 0.f) * w3q.y
                    + fmaxf(acc[i][2], 0.f) * w3q.z
                    + fmaxf(acc[i][3], 0.f) * w3q.w;
        }
    }
    // reduce over tf (16 lanes per half-warp; halves hold different edges)
#pragma unroll
    for (int off = 8; off >= 1; off >>= 1) {
#pragma unroll
        for (int i = 0; i < 8; i++)
            part[i] += __shfl_xor_sync(0xffffffffu, part[i], off);
    }
    if (tf == 0) {
#pragma unroll
        for (int i = 0; i < 8; i++)
            s_logit[ebase + i] = part[i] + b3;
    }
    __syncthreads();

    // ---- segment softmax: warp w handles node w (32 logits) ----
    if (t < TILE_E) {
        float l = s_logit[t];
        float m = l;
#pragma unroll
        for (int off = 16; off >= 1; off >>= 1)
            m = fmaxf(m, __shfl_xor_sync(0xffffffffu, m, off));
        float a = __expf(l - m);
        float s = a;
#pragma unroll
        for (int off = 16; off >= 1; off >>= 1)
            s += __shfl_xor_sync(0xffffffffu, s, off);
        s_att[t] = a / s;
    }
    __syncthreads();

    // ---- aggregation: out[node][f] = sum_e att[e] * e_u[e][f] ----
    {
        int nl = t >> 6;         // local node 0..3
        int f  = t & 63;
        int eb = nl * 32;
        float a = 0.f;
#pragma unroll
        for (int e = 0; e < 32; e++)
            a += s_att[eb + e] * s_eu[(eb + e) * D + f];
        out[(size_t)(n0 + nl) * D + f] = a;
    }
}

// ---------------------------------------------------------------------------
extern "C" void kernel_launch(void* const* d_in, const int* in_sizes, int n_in,
                              void* d_out, int out_size) {
    const int*   nodes = (const int*)  d_in[0];
    const int*   neigh = (const int*)  d_in[1];
    // d_in[2] = segment_ids: implicit (sorted, DEGREE per node) -> unused
    const float* u2e   = (const float*)d_in[3];
    const float* g2e   = (const float*)d_in[4];
    const float* w1    = (const float*)d_in[5];
    const float* b1    = (const float*)d_in[6];
    const float* w2    = (const float*)d_in[7];
    const float* b2    = (const float*)d_in[8];
    const float* w3    = (const float*)d_in[9];
    const float* b3    = (const float*)d_in[10];
    float* out = (float*)d_out;

    cudaFuncSetAttribute(k_main, cudaFuncAttributeMaxDynamicSharedMemorySize,
                         SMEM_FLOATS * (int)sizeof(float));

    k_transpose<<<16, 256>>>(w1, w2);
    k_gq<<<N_NODES / 16, 256>>>(nodes, g2e, b1);
    k_main<<<NBLK, 256, SMEM_FLOATS * sizeof(float)>>>(neigh, u2e, b2, w3, b3, out);
}

// round 5
// speedup vs baseline: 2.3680x; 2.3680x over previous
#include <cuda_runtime.h>
#include <cstdint>

#define N_NODES   40000
#define DEGREE    32
#define E_TOTAL   (N_NODES * DEGREE)
#define D         64
#define TILE_E    128                   // edges per tile = 4 whole nodes
#define NODES_PB  4
#define NBLK      (E_TOTAL / TILE_E)    // 10000
#define PERSIST   296                   // 148 SMs x 2 CTAs
#define STRIDE    68                    // padded row stride (floats): (4r+c) bank-perfect

// ---- device scratch (static allocation is allowed) ----
__device__ float    g_gq[N_NODES * D];  // per-node query preactivation (incl. b1)
__device__ float    g_w1b_t[D * D];     // att1_w[:,64:] transposed [k][f] (for k_gq)
__device__ uint32_t g_w1f[8 * 8 * 32 * 2];  // W1a in mma B-fragment order (tf32 bits)
__device__ uint32_t g_w2f[8 * 8 * 32 * 2];  // W2 in mma B-fragment order  (tf32 bits)

__device__ __forceinline__ uint32_t f2tf32(float x) {
    uint32_t u;
    asm("cvt.rna.tf32.f32 %0, %1;" : "=r"(u) : "f"(x));
    return u;
}

// ---------------------------------------------------------------------------
// Kernel 0: weight prep — fragment layout for mma + [k][f] for k_gq
// B-fragment (m16n8k8.row.col): lane T holds B[k = T%4 (+4)][n = T/4]
// stored at [((ntile*8 + kstep)*32 + lane)*2 + {0,1}]
// ---------------------------------------------------------------------------
__global__ void k_prep(const float* __restrict__ w1,
                       const float* __restrict__ w2) {
    int idx = blockIdx.x * blockDim.x + threadIdx.x;
    if (idx < 2048) {                       // 8 ntiles x 8 ksteps x 32 lanes
        int lane = idx & 31, ks = (idx >> 5) & 7, n = idx >> 8;
        int f = n * 8 + (lane >> 2);        // output feature (B column)
        int k = ks * 8 + (lane & 3);        // reduction index (B row)
        g_w1f[idx * 2 + 0] = f2tf32(w1[f * 2 * D + k]);
        g_w1f[idx * 2 + 1] = f2tf32(w1[f * 2 * D + k + 4]);
        g_w2f[idx * 2 + 0] = f2tf32(w2[f * D + k]);
        g_w2f[idx * 2 + 1] = f2tf32(w2[f * D + k + 4]);
    }
    if (idx < 4096) {                       // w1b transpose for k_gq (fp32)
        int k = idx >> 6, f = idx & 63;
        g_w1b_t[k * D + f] = w1[f * 2 * D + D + k];
    }
}

// ---------------------------------------------------------------------------
// Kernel 1: gq[n][f] = b1[f] + sum_k g2e[nodes[n]][k] * W1b[f][k]   (fp32)
// ---------------------------------------------------------------------------
__global__ __launch_bounds__(256) void k_gq(const int* __restrict__ nodes,
                                            const float* __restrict__ g2e,
                                            const float* __restrict__ b1) {
    __shared__ float s_w[D * D];
    __shared__ float s_g[16 * D];
    int t = threadIdx.x;
    int nbase = blockIdx.x * 16;

    {
        const float4* w4 = (const float4*)g_w1b_t;
        float4* s4 = (float4*)s_w;
#pragma unroll
        for (int i = t; i < D * D / 4; i += 256) s4[i] = w4[i];
    }
    for (int i = t; i < 16 * 16; i += 256) {
        int nl = i >> 4, c = i & 15;
        ((float4*)s_g)[(nl << 4) + c] =
            ((const float4*)g2e)[(size_t)nodes[nbase + nl] * 16 + c];
    }
    __syncthreads();

    int f = t & 63, ng = t >> 6;
    float bias = b1[f];
    float acc[4] = {bias, bias, bias, bias};
    for (int k = 0; k < D; k++) {
        float w = s_w[k * D + f];
#pragma unroll
        for (int j = 0; j < 4; j++)
            acc[j] += w * s_g[(ng + 4 * j) * D + k];
    }
#pragma unroll
    for (int j = 0; j < 4; j++)
        g_gq[(size_t)(nbase + ng + 4 * j) * D + f] = acc[j];
}

// ---------------------------------------------------------------------------
// tf32 mma m16n8k8 (row.col), fp32 accumulate
// ---------------------------------------------------------------------------
__device__ __forceinline__ void mma_tf32(float c[4], const uint32_t a[4],
                                         const uint32_t b[2]) {
    asm volatile(
        "mma.sync.aligned.m16n8k8.row.col.f32.tf32.tf32.f32 "
        "{%0,%1,%2,%3}, {%4,%5,%6,%7}, {%8,%9}, {%0,%1,%2,%3};"
        : "+f"(c[0]), "+f"(c[1]), "+f"(c[2]), "+f"(c[3])
        : "r"(a[0]), "r"(a[1]), "r"(a[2]), "r"(a[3]), "r"(b[0]), "r"(b[1]));
}

// per-warp GEMM step over one 128x64(xK=64) tile slice:
// warp covers 32 edges (2 m-tiles, rows mrow0..) x 32 features (4 n-tiles)
__device__ __forceinline__ void warp_gemm(const float* __restrict__ s_in,
                                          const uint32_t* __restrict__ s_wf,
                                          float acc[2][4][4],
                                          int mrow0, int wf, int r, int c,
                                          int lane) {
#pragma unroll
    for (int ks = 0; ks < 8; ks++) {
        uint32_t a[2][4];
#pragma unroll
        for (int i = 0; i < 2; i++) {
            const float* base = s_in + (mrow0 + 16 * i + r) * STRIDE + ks * 8 + c;
            a[i][0] = __float_as_uint(base[0]);
            a[i][1] = __float_as_uint(base[8 * STRIDE]);
            a[i][2] = __float_as_uint(base[4]);
            a[i][3] = __float_as_uint(base[8 * STRIDE + 4]);
        }
        uint32_t b[4][2];
#pragma unroll
        for (int j = 0; j < 4; j++) {
            int nj = 4 * wf + j;
            const uint32_t* bp = s_wf + ((nj * 8 + ks) * 32 + lane) * 2;
            uint2 bv = *(const uint2*)bp;
            b[j][0] = bv.x; b[j][1] = bv.y;
        }
#pragma unroll
        for (int i = 0; i < 2; i++)
#pragma unroll
            for (int j = 0; j < 4; j++)
                mma_tf32(acc[i][j], a[i], b[j]);
    }
}

// ---------------------------------------------------------------------------
// Kernel 2: persistent fused edge-MLP (tf32 tensor) + softmax + aggregation
// ---------------------------------------------------------------------------
// dynamic smem (floats):
//   s_eu   [0,      8704)   128 x STRIDE gathered member embeddings (fp32)
//   s_h1   [8704,  17408)   128 x STRIDE layer-1 activations
//   s_w1f  [17408, 21504)   W1a fragments (uint bits)
//   s_w2f  [21504, 25600)   W2  fragments
//   s_gq   [25600, 25856)   4 x 64
//   s_b2   [25856, 25920)
//   s_w3   [25920, 25984)
//   s_lp   [25984, 26240)   2 x 128 logit partials
//   s_att  [26240, 26368)
#define SMEM_FLOATS 26368

__global__ __launch_bounds__(256, 2) void k_main(const int*   __restrict__ neigh,
                                                 const float* __restrict__ u2e,
                                                 const float* __restrict__ b2v,
                                                 const float* __restrict__ w3v,
                                                 const float* __restrict__ b3v,
                                                 float* __restrict__ out) {
    extern __shared__ float sm[];
    float*    s_eu  = sm;
    float*    s_h1  = sm + 8704;
    uint32_t* s_w1f = (uint32_t*)(sm + 17408);
    uint32_t* s_w2f = (uint32_t*)(sm + 21504);
    float*    s_gq  = sm + 25600;
    float*    s_b2  = sm + 25856;
    float*    s_w3  = sm + 25920;
    float*    s_lp  = sm + 25984;
    float*    s_att = sm + 26240;

    int t    = threadIdx.x;
    int lane = t & 31;
    int w    = t >> 5;
    int we   = w >> 1;          // edge group 0..3 == local node
    int wf   = w & 1;           // feature half 0..1
    int r    = lane >> 2;       // mma groupID
    int c    = lane & 3;        // mma threadID_in_group
    int mrow0 = 32 * we;

    // ---- one-time staging: weight fragments + small vectors ----
    {
        const uint4* w1v = (const uint4*)g_w1f;
        const uint4* w2v = (const uint4*)g_w2f;
        uint4* d1 = (uint4*)s_w1f;
        uint4* d2 = (uint4*)s_w2f;
#pragma unroll
        for (int i = t; i < 1024; i += 256) { d1[i] = w1v[i]; d2[i] = w2v[i]; }
    }
    if (t < 64) { s_b2[t] = b2v[t]; s_w3[t] = w3v[t]; }
    float b3 = b3v[0];

    for (int tile = blockIdx.x; tile < NBLK; tile += PERSIST) {
        int e0 = tile * TILE_E;
        int n0 = tile * NODES_PB;

        // ---- phase 1: gather e_u + per-node query term ----
        s_gq[t] = g_gq[(size_t)n0 * D + t];
        {
            const float4* u2e4 = (const float4*)u2e;
#pragma unroll
            for (int i = t; i < 2048; i += 256) {
                int row = i >> 4, cc = i & 15;
                int uid = neigh[e0 + row];
                *(float4*)(s_eu + row * STRIDE + cc * 4) =
                    u2e4[(size_t)uid * 16 + cc];
            }
        }
        __syncthreads();

        // ---- phase 2: GEMM1  h1 = relu(e_u @ W1a^T + gq[node]) ----
        {
            float acc[2][4][4];
#pragma unroll
            for (int j = 0; j < 4; j++) {
                int colA = 32 * wf + 8 * j + 2 * c;
                float q0 = s_gq[we * D + colA];
                float q1 = s_gq[we * D + colA + 1];
#pragma unroll
                for (int i = 0; i < 2; i++) {
                    acc[i][j][0] = q0; acc[i][j][1] = q1;
                    acc[i][j][2] = q0; acc[i][j][3] = q1;
                }
            }
            warp_gemm(s_eu, s_w1f, acc, mrow0, wf, r, c, lane);
#pragma unroll
            for (int i = 0; i < 2; i++) {
                int row = mrow0 + 16 * i + r;
#pragma unroll
                for (int j = 0; j < 4; j++) {
                    int colA = 32 * wf + 8 * j + 2 * c;
                    float2 v0 = { fmaxf(acc[i][j][0], 0.f), fmaxf(acc[i][j][1], 0.f) };
                    float2 v1 = { fmaxf(acc[i][j][2], 0.f), fmaxf(acc[i][j][3], 0.f) };
                    *(float2*)(s_h1 + row * STRIDE + colA)       = v0;
                    *(float2*)(s_h1 + (row + 8) * STRIDE + colA) = v1;
                }
            }
        }
        __syncthreads();

        // ---- phase 3: GEMM2 + logits = relu(h2) . w3 ----
        {
            float acc[2][4][4];
#pragma unroll
            for (int j = 0; j < 4; j++) {
                int colA = 32 * wf + 8 * j + 2 * c;
                float2 b2p = *(const float2*)(s_b2 + colA);
#pragma unroll
                for (int i = 0; i < 2; i++) {
                    acc[i][j][0] = b2p.x; acc[i][j][1] = b2p.y;
                    acc[i][j][2] = b2p.x; acc[i][j][3] = b2p.y;
                }
            }
            warp_gemm(s_h1, s_w2f, acc, mrow0, wf, r, c, lane);

            float p0[2] = {0.f, 0.f}, p1[2] = {0.f, 0.f};
#pragma unroll
            for (int j = 0; j < 4; j++) {
                int colA = 32 * wf + 8 * j + 2 * c;
                float2 w3p = *(const float2*)(s_w3 + colA);
#pragma unroll
                for (int i = 0; i < 2; i++) {
                    p0[i] += fmaxf(acc[i][j][0], 0.f) * w3p.x
                           + fmaxf(acc[i][j][1], 0.f) * w3p.y;
                    p1[i] += fmaxf(acc[i][j][2], 0.f) * w3p.x
                           + fmaxf(acc[i][j][3], 0.f) * w3p.y;
                }
            }
#pragma unroll
            for (int off = 1; off <= 2; off <<= 1) {
#pragma unroll
                for (int i = 0; i < 2; i++) {
                    p0[i] += __shfl_xor_sync(0xffffffffu, p0[i], off);
                    p1[i] += __shfl_xor_sync(0xffffffffu, p1[i], off);
                }
            }
            if (c == 0) {
#pragma unroll
                for (int i = 0; i < 2; i++) {
                    int row = mrow0 + 16 * i + r;
                    s_lp[wf * 128 + row]     = p0[i];
                    s_lp[wf * 128 + row + 8] = p1[i];
                }
            }
        }
        __syncthreads();

        // ---- phase 4: segment softmax (warp = node) ----
        if (t < TILE_E) {
            float l = s_lp[t] + s_lp[128 + t] + b3;
            float m = l;
#pragma unroll
            for (int off = 16; off >= 1; off >>= 1)
                m = fmaxf(m, __shfl_xor_sync(0xffffffffu, m, off));
            float a = __expf(l - m);
            float s = a;
#pragma unroll
            for (int off = 16; off >= 1; off >>= 1)
                s += __shfl_xor_sync(0xffffffffu, s, off);
            s_att[t] = a / s;
        }
        __syncthreads();

        // ---- phase 5: aggregation out[node][f] = sum_e att[e]*e_u[e][f] ----
        {
            int nl = t >> 6;
            int f  = t & 63;
            int eb = nl * 32;
            float a = 0.f;
#pragma unroll
            for (int e = 0; e < 32; e++)
                a += s_att[eb + e] * s_eu[(eb + e) * STRIDE + f];
            out[(size_t)(n0 + nl) * D + f] = a;
        }
        __syncthreads();   // protect s_eu/s_att before next tile overwrites
    }
}

// ---------------------------------------------------------------------------
extern "C" void kernel_launch(void* const* d_in, const int* in_sizes, int n_in,
                              void* d_out, int out_size) {
    const int*   nodes = (const int*)  d_in[0];
    const int*   neigh = (const int*)  d_in[1];
    // d_in[2] = segment_ids: implicit (sorted, DEGREE per node) -> unused
    const float* u2e   = (const float*)d_in[3];
    const float* g2e   = (const float*)d_in[4];
    const float* w1    = (const float*)d_in[5];
    const float* b1    = (const float*)d_in[6];
    const float* w2    = (const float*)d_in[7];
    const float* b2    = (const float*)d_in[8];
    const float* w3    = (const float*)d_in[9];
    const float* b3    = (const float*)d_in[10];
    float* out = (float*)d_out;

    cudaFuncSetAttribute(k_main, cudaFuncAttributeMaxDynamicSharedMemorySize,
                         SMEM_FLOATS * (int)sizeof(float));

    k_prep<<<16, 256>>>(w1, w2);
    k_gq<<<N_NODES / 16, 256>>>(nodes, g2e, b1);
    k_main<<<PERSIST, 256, SMEM_FLOATS * sizeof(float)>>>(neigh, u2e, b2, w3, b3, out);
}